// round 1
// baseline (speedup 1.0000x reference)
#include <cuda_runtime.h>
#include <math.h>

#define NN 40000
#define CC 128
#define HH 4
#define EE 200000
#define TS (1u<<19)
#define TMASK (TS-1u)
#define PADW 132
#define SMEMB ((64+128)*PADW*4)

// ---------------- scratch (device globals; no runtime allocation) ----------------
__device__ float g_Qu[NN*CC], g_Ku[NN*CC], g_Vu[NN*CC];
__device__ float g_Qi[NN*CC], g_Ki[NN*CC], g_Vi[NN*CC];
__device__ float g_agg_u[NN*CC], g_agg_i[NN*CC];
__device__ float g_z_u[NN*HH], g_z_i[NN*HH];
__device__ int g_ck_ui[TS], g_cv_ui[TS];
__device__ int g_ck_iu[TS], g_cv_iu[TS];
__device__ int g_rk_ui[TS], g_rk_iu[TS];
__device__ int g_deg_u[NN], g_deg_i[NN], g_indeg_u[NN], g_indeg_i[NN];

// ---------------- hash helpers ----------------
__device__ __forceinline__ unsigned hmix(int k){
  unsigned x = (unsigned)k;
  x *= 2654435761u;
  x ^= x >> 15;
  return x & TMASK;
}
__device__ __forceinline__ void hinsert_count(int* keys, int* vals, int key){
  unsigned slot = hmix(key);
  while (true){
    int prev = atomicCAS(&keys[slot], -1, key);
    if (prev == -1 || prev == key){ atomicAdd(&vals[slot], 1); return; }
    slot = (slot + 1) & TMASK;
  }
}
__device__ __forceinline__ void hinsert_set(int* keys, int key){
  unsigned slot = hmix(key);
  while (true){
    int prev = atomicCAS(&keys[slot], -1, key);
    if (prev == -1 || prev == key) return;
    slot = (slot + 1) & TMASK;
  }
}
__device__ __forceinline__ int hcount(const int* __restrict__ keys, const int* __restrict__ vals, int key){
  unsigned slot = hmix(key);
  while (true){
    int k = keys[slot];
    if (k == key) return vals[slot];
    if (k == -1) return 0;
    slot = (slot + 1) & TMASK;
  }
}
__device__ __forceinline__ bool hmember(const int* __restrict__ keys, int key){
  unsigned slot = hmix(key);
  while (true){
    int k = keys[slot];
    if (k == key) return true;
    if (k == -1) return false;
    slot = (slot + 1) & TMASK;
  }
}

// ---------------- init ----------------
__global__ void k_init(){
  int i = blockIdx.x*blockDim.x + threadIdx.x;
  int stride = gridDim.x*blockDim.x;
  for (int j=i;j<NN*CC;j+=stride){ g_agg_u[j]=0.f; g_agg_i[j]=0.f; }
  for (int j=i;j<(int)TS;j+=stride){
    g_ck_ui[j]=-1; g_ck_iu[j]=-1; g_rk_ui[j]=-1; g_rk_iu[j]=-1;
    g_cv_ui[j]=0;  g_cv_iu[j]=0;
  }
  for (int j=i;j<NN*HH;j+=stride){ g_z_u[j]=0.f; g_z_i[j]=0.f; }
  for (int j=i;j<NN;j+=stride){ g_deg_u[j]=0; g_deg_i[j]=0; g_indeg_u[j]=0; g_indeg_i[j]=0; }
}

// ---------------- hash/degree build ----------------
__global__ void k_build(const int* __restrict__ eui, const int* __restrict__ eiu){
  int i = blockIdx.x*blockDim.x + threadIdx.x;
  if (i < EE){
    int su = eui[i], du = eui[EE+i];
    hinsert_count(g_ck_ui, g_cv_ui, su*NN + du);   // pid_ui
    hinsert_set  (g_rk_iu, du*NN + su);            // rev_for_iu
    atomicAdd(&g_deg_u[su],1); atomicAdd(&g_deg_i[du],1); atomicAdd(&g_indeg_i[du],1);
  } else if (i < 2*EE){
    int j = i - EE;
    int si = eiu[j], di = eiu[EE+j];
    hinsert_count(g_ck_iu, g_cv_iu, si*NN + di);   // pid_iu
    hinsert_set  (g_rk_ui, di*NN + si);            // rev_for_ui
    atomicAdd(&g_deg_i[si],1); atomicAdd(&g_deg_u[di],1); atomicAdd(&g_indeg_u[di],1);
  }
}

// ---------------- GEMM: Y[M,128] = X[M,128] @ W^T + b  (W is [128 out][128 in]) ----------------
__global__ void k_gemm(const float* __restrict__ X, const float* __restrict__ W,
                       const float* __restrict__ bias, float* __restrict__ Y){
  extern __shared__ float sm[];
  float* Xs = sm;             // [64][PADW]
  float* Ws = sm + 64*PADW;   // [128][PADW], row = out-col, contiguous k
  int tid = threadIdx.x;
  int row0 = blockIdx.x*64;
  for (int i=tid;i<CC*CC;i+=256){
    int col=i>>7, k=i&127;
    Ws[col*PADW + k] = W[i];
  }
  for (int i=tid;i<64*CC;i+=256){
    int r=i>>7, c=i&127;
    Xs[r*PADW + c] = X[(row0+r)*CC + c];
  }
  __syncthreads();
  int tx = tid & 15, ty = tid >> 4;   // tx -> cols (tx+16j), ty -> rows (ty*4+i)
  float acc[4][8];
  #pragma unroll
  for (int i=0;i<4;i++)
    #pragma unroll
    for (int j=0;j<8;j++) acc[i][j]=0.f;
  const float4* Xs4 = (const float4*)Xs;
  const float4* Ws4 = (const float4*)Ws;
  #pragma unroll 2
  for (int k4=0;k4<32;k4++){
    float4 a[4];
    #pragma unroll
    for (int i=0;i<4;i++) a[i] = Xs4[(ty*4+i)*(PADW/4) + k4];
    float4 w[8];
    #pragma unroll
    for (int j=0;j<8;j++) w[j] = Ws4[(tx+16*j)*(PADW/4) + k4];
    #pragma unroll
    for (int i=0;i<4;i++)
      #pragma unroll
      for (int j=0;j<8;j++)
        acc[i][j] += a[i].x*w[j].x + a[i].y*w[j].y + a[i].z*w[j].z + a[i].w*w[j].w;
  }
  #pragma unroll
  for (int i=0;i<4;i++){
    int gr = row0 + ty*4 + i;
    #pragma unroll
    for (int j=0;j<8;j++){
      int c = tx + 16*j;
      Y[gr*CC + c] = acc[i][j] + bias[c];
    }
  }
}

// ---------------- edge kernel: scores + exp + z accumulation + V scatter ----------------
__global__ void k_edge(const int* __restrict__ src, const int* __restrict__ dst,
                       const float* __restrict__ Q, const float* __restrict__ K,
                       const float* __restrict__ V,
                       const float* __restrict__ t_src, const float* __restrict__ t_dst,
                       const int* __restrict__ ckeys, const int* __restrict__ cvals,
                       const int* __restrict__ rkeys,
                       const float* __restrict__ hb, const float* __restrict__ beta,
                       const float* __restrict__ tau_raw,
                       const float* __restrict__ gamma, const float* __restrict__ delta,
                       float* __restrict__ z, float* __restrict__ agg){
  int e = blockIdx.x*8 + (threadIdx.x>>5);
  int lane = threadIdx.x & 31;
  int s = src[e], d = dst[e];
  float4 q = __ldg((const float4*)(Q + (size_t)d*CC) + lane);
  float4 k = __ldg((const float4*)(K + (size_t)s*CC) + lane);
  float4 v = __ldg((const float4*)(V + (size_t)s*CC) + lane);
  float p = q.x*k.x + q.y*k.y + q.z*k.z + q.w*k.w;
  p += __shfl_xor_sync(0xffffffffu, p, 1);
  p += __shfl_xor_sync(0xffffffffu, p, 2);
  p += __shfl_xor_sync(0xffffffffu, p, 4);   // head-local dot, identical in each 8-lane group
  float tl=0.f, lc=0.f, rec=0.f;
  if (lane == 0){
    float traw = tau_raw[0];
    float tau = (traw > 20.f) ? traw : log1pf(expf(traw));
    tau += 1e-6f;
    float dt = fabsf(t_dst[d] - t_src[s]) + 1e-6f;
    tl = -log1pf(dt / tau);
    int pid = s*NN + d;
    int cnt = hcount(ckeys, cvals, pid) - 1;
    lc = log1pf((float)cnt);
    rec = hmember(rkeys, pid) ? 1.f : 0.f;
  }
  tl  = __shfl_sync(0xffffffffu, tl, 0);
  lc  = __shfl_sync(0xffffffffu, lc, 0);
  rec = __shfl_sync(0xffffffffu, rec, 0);
  int h = lane >> 3;
  float score = p * 0.17677669529663687f + hb[h] + tl*beta[h] + lc*gamma[h] + rec*delta[h];
  float w = expf(score);
  if ((lane & 7) == 0) atomicAdd(&z[(size_t)d*HH + h], w);
  float* ab = agg + (size_t)d*CC + lane*4;
  atomicAdd(ab+0, v.x*w);
  atomicAdd(ab+1, v.y*w);
  atomicAdd(ab+2, v.z*w);
  atomicAdd(ab+3, v.w*w);
}

// ---------------- epilogue: (agg/z) @ Wo^T + indeg*bo + deg + x, then layernorm ----------------
__global__ void k_out(const float* __restrict__ agg, const float* __restrict__ z,
                      const float* __restrict__ W, const float* __restrict__ bias,
                      const int* __restrict__ indeg, const int* __restrict__ deg,
                      const float* __restrict__ xres, float* __restrict__ out){
  extern __shared__ float sm[];
  float* As = sm;
  float* Ws = sm + 64*PADW;
  int tid = threadIdx.x;
  int row0 = blockIdx.x*64;
  for (int i=tid;i<CC*CC;i+=256){
    int col=i>>7, k=i&127;
    Ws[col*PADW + k] = W[i];
  }
  for (int i=tid;i<64*CC;i+=256){
    int r=i>>7, c=i&127;
    int gr = row0 + r;
    float zz = z[(size_t)gr*HH + (c>>5)];
    float a = agg[(size_t)gr*CC + c];
    As[r*PADW + c] = (zz > 0.f) ? (a/zz) : 0.f;
  }
  __syncthreads();
  int tx = tid & 15, ty = tid >> 4;
  float acc[4][8];
  #pragma unroll
  for (int i=0;i<4;i++)
    #pragma unroll
    for (int j=0;j<8;j++) acc[i][j]=0.f;
  const float4* As4 = (const float4*)As;
  const float4* Ws4 = (const float4*)Ws;
  #pragma unroll 2
  for (int k4=0;k4<32;k4++){
    float4 a[4];
    #pragma unroll
    for (int i=0;i<4;i++) a[i] = As4[(ty*4+i)*(PADW/4) + k4];
    float4 w[8];
    #pragma unroll
    for (int j=0;j<8;j++) w[j] = Ws4[(tx+16*j)*(PADW/4) + k4];
    #pragma unroll
    for (int i=0;i<4;i++)
      #pragma unroll
      for (int j=0;j<8;j++)
        acc[i][j] += a[i].x*w[j].x + a[i].y*w[j].y + a[i].z*w[j].z + a[i].w*w[j].w;
  }
  #pragma unroll
  for (int i=0;i<4;i++){
    int gr = row0 + ty*4 + i;
    float dg  = (float)deg[gr];
    float idg = (float)indeg[gr];
    float v[8];
    float s = 0.f;
    #pragma unroll
    for (int j=0;j<8;j++){
      int c = tx + 16*j;
      v[j] = acc[i][j] + bias[c]*idg + dg + xres[(size_t)gr*CC + c];
      s += v[j];
    }
    #pragma unroll
    for (int o=8;o>0;o>>=1) s += __shfl_xor_sync(0xffffffffu, s, o);
    float mu = s * (1.f/128.f);
    float qv = 0.f;
    #pragma unroll
    for (int j=0;j<8;j++){ float dd = v[j]-mu; qv += dd*dd; }
    #pragma unroll
    for (int o=8;o>0;o>>=1) qv += __shfl_xor_sync(0xffffffffu, qv, o);
    float rs = rsqrtf(qv*(1.f/128.f) + 1e-5f);
    #pragma unroll
    for (int j=0;j<8;j++){
      int c = tx + 16*j;
      out[(size_t)gr*CC + c] = (v[j]-mu)*rs;
    }
  }
}

// ---------------- launch ----------------
extern "C" void kernel_launch(void* const* d_in, const int* in_sizes, int n_in,
                              void* d_out, int out_size){
  const float* x_user=(const float*)d_in[0];
  const float* x_item=(const float*)d_in[1];
  const float* t_user=(const float*)d_in[2];
  const float* t_item=(const float*)d_in[3];
  const int*   eui  =(const int*)  d_in[4];
  const int*   eiu  =(const int*)  d_in[5];
  const float* Wq=(const float*)d_in[6];  const float* bq=(const float*)d_in[7];
  const float* Wk=(const float*)d_in[8];  const float* bk=(const float*)d_in[9];
  const float* Wv=(const float*)d_in[10]; const float* bv=(const float*)d_in[11];
  const float* Wo=(const float*)d_in[12]; const float* bo=(const float*)d_in[13];
  const float* hb=(const float*)d_in[14];
  const float* tb=(const float*)d_in[15];
  const float* traw=(const float*)d_in[16];
  const float* gm=(const float*)d_in[17];
  const float* dr=(const float*)d_in[18];
  float* out=(float*)d_out;

  float *Qu,*Ku,*Vu,*Qi,*Ki,*Vi,*aggu,*aggi,*zu,*zi;
  int *cku,*cvu,*cki,*cvi,*rku,*rki,*degu,*degi,*idgu,*idgi;
  cudaGetSymbolAddress((void**)&Qu, g_Qu);
  cudaGetSymbolAddress((void**)&Ku, g_Ku);
  cudaGetSymbolAddress((void**)&Vu, g_Vu);
  cudaGetSymbolAddress((void**)&Qi, g_Qi);
  cudaGetSymbolAddress((void**)&Ki, g_Ki);
  cudaGetSymbolAddress((void**)&Vi, g_Vi);
  cudaGetSymbolAddress((void**)&aggu, g_agg_u);
  cudaGetSymbolAddress((void**)&aggi, g_agg_i);
  cudaGetSymbolAddress((void**)&zu, g_z_u);
  cudaGetSymbolAddress((void**)&zi, g_z_i);
  cudaGetSymbolAddress((void**)&cku, g_ck_ui);
  cudaGetSymbolAddress((void**)&cvu, g_cv_ui);
  cudaGetSymbolAddress((void**)&cki, g_ck_iu);
  cudaGetSymbolAddress((void**)&cvi, g_cv_iu);
  cudaGetSymbolAddress((void**)&rku, g_rk_ui);
  cudaGetSymbolAddress((void**)&rki, g_rk_iu);
  cudaGetSymbolAddress((void**)&degu, g_deg_u);
  cudaGetSymbolAddress((void**)&degi, g_deg_i);
  cudaGetSymbolAddress((void**)&idgu, g_indeg_u);
  cudaGetSymbolAddress((void**)&idgi, g_indeg_i);

  cudaFuncSetAttribute(k_gemm, cudaFuncAttributeMaxDynamicSharedMemorySize, SMEMB);
  cudaFuncSetAttribute(k_out,  cudaFuncAttributeMaxDynamicSharedMemorySize, SMEMB);

  k_init<<<2048,256>>>();
  k_build<<<(2*EE+255)/256,256>>>(eui, eiu);

  // QKV projections (6 GEMMs)
  k_gemm<<<625,256,SMEMB>>>(x_item, Wq, bq, Qi);
  k_gemm<<<625,256,SMEMB>>>(x_user, Wk, bk, Ku);
  k_gemm<<<625,256,SMEMB>>>(x_user, Wv, bv, Vu);
  k_gemm<<<625,256,SMEMB>>>(x_user, Wq, bq, Qu);
  k_gemm<<<625,256,SMEMB>>>(x_item, Wk, bk, Ki);
  k_gemm<<<625,256,SMEMB>>>(x_item, Wv, bv, Vi);

  // relation user->item (rel 0): Q from items (dst), K/V from users (src)
  k_edge<<<EE/8,256>>>(eui, eui+EE, Qi, Ku, Vu, t_user, t_item,
                       cku, cvu, rku, hb, tb, traw, gm, dr, zi, aggi);
  // relation item->user (rel 1)
  k_edge<<<EE/8,256>>>(eiu, eiu+EE, Qu, Ki, Vi, t_item, t_user,
                       cki, cvi, rki, hb+HH, tb+HH, traw+1, gm+HH, dr+HH, zu, aggu);

  // fused Wo + indeg*bo + deg + residual + layernorm
  k_out<<<625,256,SMEMB>>>(aggu, zu, Wo, bo, idgu, degu, x_user, out);
  k_out<<<625,256,SMEMB>>>(aggi, zi, Wo, bo, idgi, degi, x_item, out + (size_t)NN*CC);
}

// round 3
// speedup vs baseline: 1.1669x; 1.1669x over previous
#include <cuda_runtime.h>
#include <cuda_bf16.h>
#include <math.h>
#include <stdint.h>

#define NN 40000
#define CC 128
#define HH 4
#define EE 200000
#define TS (1u<<19)
#define TMASK (TS-1u)

#define MT 128
#define NBLK ((NN + MT - 1) / MT)        // 313
#define PITCH 68
// uint32 offsets in dynamic smem
#define AHI 0
#define ALO 8704
#define BHI 17408
#define BLO 26112
#define REDS 34816
#define REDQ 35072
#define SMEMW 35328
#define SMEMB (SMEMW*4)

// ---------------- scratch (device globals) ----------------
__device__ float g_Qu[NN*CC], g_Ku[NN*CC], g_Vu[NN*CC];
__device__ float g_Qi[NN*CC], g_Ki[NN*CC], g_Vi[NN*CC];
__device__ float g_agg_u[NN*CC], g_agg_i[NN*CC];
__device__ float g_z_u[NN*HH], g_z_i[NN*HH];
__device__ int g_ck_ui[TS], g_cv_ui[TS];
__device__ int g_ck_iu[TS], g_cv_iu[TS];
__device__ int g_rk_ui[TS], g_rk_iu[TS];
__device__ int g_deg_u[NN], g_deg_i[NN], g_indeg_u[NN], g_indeg_i[NN];

// ---------------- bf16 split + mma helpers ----------------
__device__ __forceinline__ void bsplit(float a, float b, uint32_t& hi, uint32_t& lo){
  __nv_bfloat16 ha = __float2bfloat16(a), hb = __float2bfloat16(b);
  float ra = a - __bfloat162float(ha);
  float rb = b - __bfloat162float(hb);
  __nv_bfloat16 la = __float2bfloat16(ra), lb = __float2bfloat16(rb);
  hi = ((uint32_t)__bfloat16_as_ushort(hb) << 16) | (uint32_t)__bfloat16_as_ushort(ha);
  lo = ((uint32_t)__bfloat16_as_ushort(lb) << 16) | (uint32_t)__bfloat16_as_ushort(la);
}

__device__ __forceinline__ void mma_bf16(float* c,
    uint32_t a0, uint32_t a1, uint32_t a2, uint32_t a3,
    uint32_t b0, uint32_t b1){
  asm volatile("mma.sync.aligned.m16n8k16.row.col.f32.bf16.bf16.f32 "
    "{%0,%1,%2,%3}, {%4,%5,%6,%7}, {%8,%9}, {%0,%1,%2,%3};"
    : "+f"(c[0]), "+f"(c[1]), "+f"(c[2]), "+f"(c[3])
    : "r"(a0), "r"(a1), "r"(a2), "r"(a3), "r"(b0), "r"(b1));
}

// stage a [128 x 128] fp32 matrix as split bf16x2 planes into smem
__device__ __forceinline__ void stage_mat(uint32_t* sm, int hioff, int looff,
                                          const float* __restrict__ src,
                                          int row0, bool guard){
  int tid = threadIdx.x;
  #pragma unroll
  for (int it = 0; it < 32; it++){
    int idx = tid + it*256;
    int row = idx >> 6, j = idx & 63;
    float2 v = make_float2(0.f, 0.f);
    int gr = row0 + row;
    if (!guard || gr < NN) v = *(const float2*)(src + (size_t)gr*CC + j*2);
    uint32_t hi, lo;
    bsplit(v.x, v.y, hi, lo);
    sm[hioff + row*PITCH + j] = hi;
    sm[looff + row*PITCH + j] = lo;
  }
}

// core: acc[2][8][4] += A(128x128) @ B^T (B stored as [n][k]) for this warp's tile
__device__ __forceinline__ void mma_core(const uint32_t* sm, float acc[2][8][4],
                                         int mw, int nw, int tg, int tq){
  #pragma unroll
  for (int s = 0; s < 8; s++){
    int k2 = s*8 + tq;
    uint32_t ah[2][4], al[2][4];
    #pragma unroll
    for (int mt = 0; mt < 2; mt++){
      int r = mw*32 + mt*16 + tg;
      ah[mt][0] = sm[AHI + r*PITCH + k2];
      ah[mt][1] = sm[AHI + (r+8)*PITCH + k2];
      ah[mt][2] = sm[AHI + r*PITCH + k2 + 4];
      ah[mt][3] = sm[AHI + (r+8)*PITCH + k2 + 4];
      al[mt][0] = sm[ALO + r*PITCH + k2];
      al[mt][1] = sm[ALO + (r+8)*PITCH + k2];
      al[mt][2] = sm[ALO + r*PITCH + k2 + 4];
      al[mt][3] = sm[ALO + (r+8)*PITCH + k2 + 4];
    }
    #pragma unroll
    for (int nt = 0; nt < 8; nt++){
      int n = nw*64 + nt*8 + tg;
      uint32_t bh0 = sm[BHI + n*PITCH + k2];
      uint32_t bh1 = sm[BHI + n*PITCH + k2 + 4];
      uint32_t bl0 = sm[BLO + n*PITCH + k2];
      uint32_t bl1 = sm[BLO + n*PITCH + k2 + 4];
      #pragma unroll
      for (int mt = 0; mt < 2; mt++){
        mma_bf16(acc[mt][nt], ah[mt][0], ah[mt][1], ah[mt][2], ah[mt][3], bh0, bh1);
        mma_bf16(acc[mt][nt], ah[mt][0], ah[mt][1], ah[mt][2], ah[mt][3], bl0, bl1);
        mma_bf16(acc[mt][nt], al[mt][0], al[mt][1], al[mt][2], al[mt][3], bh0, bh1);
      }
    }
  }
}

// ---------------- hash helpers ----------------
__device__ __forceinline__ unsigned hmix(int k){
  unsigned x = (unsigned)k; x *= 2654435761u; x ^= x >> 15; return x & TMASK;
}
__device__ __forceinline__ void hinsert_count(int* keys, int* vals, int key){
  unsigned slot = hmix(key);
  while (true){
    int prev = atomicCAS(&keys[slot], -1, key);
    if (prev == -1 || prev == key){ atomicAdd(&vals[slot], 1); return; }
    slot = (slot + 1) & TMASK;
  }
}
__device__ __forceinline__ void hinsert_set(int* keys, int key){
  unsigned slot = hmix(key);
  while (true){
    int prev = atomicCAS(&keys[slot], -1, key);
    if (prev == -1 || prev == key) return;
    slot = (slot + 1) & TMASK;
  }
}
__device__ __forceinline__ int hcount(const int* __restrict__ keys, const int* __restrict__ vals, int key){
  unsigned slot = hmix(key);
  while (true){
    int k = keys[slot];
    if (k == key) return vals[slot];
    if (k == -1) return 0;
    slot = (slot + 1) & TMASK;
  }
}
__device__ __forceinline__ bool hmember(const int* __restrict__ keys, int key){
  unsigned slot = hmix(key);
  while (true){
    int k = keys[slot];
    if (k == key) return true;
    if (k == -1) return false;
    slot = (slot + 1) & TMASK;
  }
}

// ---------------- init ----------------
__global__ void k_init(){
  int i = blockIdx.x*blockDim.x + threadIdx.x;
  int stride = gridDim.x*blockDim.x;
  for (int j=i;j<NN*CC;j+=stride){ g_agg_u[j]=0.f; g_agg_i[j]=0.f; }
  for (int j=i;j<(int)TS;j+=stride){
    g_ck_ui[j]=-1; g_ck_iu[j]=-1; g_rk_ui[j]=-1; g_rk_iu[j]=-1;
    g_cv_ui[j]=0;  g_cv_iu[j]=0;
  }
  for (int j=i;j<NN*HH;j+=stride){ g_z_u[j]=0.f; g_z_i[j]=0.f; }
  for (int j=i;j<NN;j+=stride){ g_deg_u[j]=0; g_deg_i[j]=0; g_indeg_u[j]=0; g_indeg_i[j]=0; }
}

// ---------------- hash/degree build ----------------
__global__ void k_build(const int* __restrict__ eui, const int* __restrict__ eiu){
  int i = blockIdx.x*blockDim.x + threadIdx.x;
  if (i < EE){
    int su = eui[i], du = eui[EE+i];
    hinsert_count(g_ck_ui, g_cv_ui, su*NN + du);
    hinsert_set  (g_rk_iu, du*NN + su);
    atomicAdd(&g_deg_u[su],1); atomicAdd(&g_deg_i[du],1); atomicAdd(&g_indeg_i[du],1);
  } else if (i < 2*EE){
    int j = i - EE;
    int si = eiu[j], di = eiu[EE+j];
    hinsert_count(g_ck_iu, g_cv_iu, si*NN + di);
    hinsert_set  (g_rk_ui, di*NN + si);
    atomicAdd(&g_deg_i[si],1); atomicAdd(&g_deg_u[di],1); atomicAdd(&g_indeg_u[di],1);
  }
}

// ---------------- fused QKV GEMMs via mma.sync bf16-split ----------------
__global__ __launch_bounds__(256,1) void k_qkv3(
    const float* __restrict__ X,
    const float* __restrict__ Wq, const float* __restrict__ Wk, const float* __restrict__ Wv,
    const float* __restrict__ bq, const float* __restrict__ bk, const float* __restrict__ bv,
    float* __restrict__ Yq, float* __restrict__ Yk, float* __restrict__ Yv){
  extern __shared__ uint32_t sm[];
  int tid = threadIdx.x, lane = tid & 31, wid = tid >> 5;
  int mw = wid & 3, nw = wid >> 2, tg = lane >> 2, tq = lane & 3;
  int row0 = blockIdx.x * MT;

  stage_mat(sm, AHI, ALO, X, row0, true);

  const float* Ws[3] = {Wq, Wk, Wv};
  const float* bs[3] = {bq, bk, bv};
  float* Ys[3] = {Yq, Yk, Yv};

  for (int m = 0; m < 3; m++){
    stage_mat(sm, BHI, BLO, Ws[m], 0, false);
    __syncthreads();

    float acc[2][8][4];
    #pragma unroll
    for (int a=0;a<2;a++)
      #pragma unroll
      for (int b=0;b<8;b++)
        #pragma unroll
        for (int c=0;c<4;c++) acc[a][b][c]=0.f;

    mma_core(sm, acc, mw, nw, tg, tq);

    const float* bias = bs[m];
    float* Y = Ys[m];
    #pragma unroll
    for (int mt = 0; mt < 2; mt++){
      int r = row0 + mw*32 + mt*16 + tg;
      #pragma unroll
      for (int nt = 0; nt < 8; nt++){
        int col = nw*64 + nt*8 + tq*2;
        float2 bb = *(const float2*)(bias + col);
        if (r < NN)
          *(float2*)(Y + (size_t)r*CC + col) = make_float2(acc[mt][nt][0]+bb.x, acc[mt][nt][1]+bb.y);
        if (r + 8 < NN)
          *(float2*)(Y + (size_t)(r+8)*CC + col) = make_float2(acc[mt][nt][2]+bb.x, acc[mt][nt][3]+bb.y);
      }
    }
    __syncthreads();
  }
}

// ---------------- edge kernel ----------------
__global__ void k_edge(const int* __restrict__ src, const int* __restrict__ dst,
                       const float* __restrict__ Q, const float* __restrict__ K,
                       const float* __restrict__ V,
                       const float* __restrict__ t_src, const float* __restrict__ t_dst,
                       const int* __restrict__ ckeys, const int* __restrict__ cvals,
                       const int* __restrict__ rkeys,
                       const float* __restrict__ hb, const float* __restrict__ beta,
                       const float* __restrict__ tau_raw,
                       const float* __restrict__ gamma, const float* __restrict__ delta,
                       float* __restrict__ z, float* __restrict__ agg){
  int e = blockIdx.x*8 + (threadIdx.x>>5);
  int lane = threadIdx.x & 31;
  int s = src[e], d = dst[e];
  float4 q = __ldg((const float4*)(Q + (size_t)d*CC) + lane);
  float4 k = __ldg((const float4*)(K + (size_t)s*CC) + lane);
  float4 v = __ldg((const float4*)(V + (size_t)s*CC) + lane);
  float p = q.x*k.x + q.y*k.y + q.z*k.z + q.w*k.w;
  p += __shfl_xor_sync(0xffffffffu, p, 1);
  p += __shfl_xor_sync(0xffffffffu, p, 2);
  p += __shfl_xor_sync(0xffffffffu, p, 4);
  float tl=0.f, lc=0.f, rec=0.f;
  if (lane == 0){
    float traw = tau_raw[0];
    float tau = (traw > 20.f) ? traw : log1pf(expf(traw));
    tau += 1e-6f;
    float dt = fabsf(t_dst[d] - t_src[s]) + 1e-6f;
    tl = -log1pf(dt / tau);
    int pid = s*NN + d;
    int cnt = hcount(ckeys, cvals, pid) - 1;
    lc = log1pf((float)cnt);
    rec = hmember(rkeys, pid) ? 1.f : 0.f;
  }
  tl  = __shfl_sync(0xffffffffu, tl, 0);
  lc  = __shfl_sync(0xffffffffu, lc, 0);
  rec = __shfl_sync(0xffffffffu, rec, 0);
  int h = lane >> 3;
  float score = p * 0.17677669529663687f + hb[h] + tl*beta[h] + lc*gamma[h] + rec*delta[h];
  float w = expf(score);
  if ((lane & 7) == 0) atomicAdd(&z[(size_t)d*HH + h], w);
  float* ab = agg + (size_t)d*CC + lane*4;
  atomicAdd(ab+0, v.x*w);
  atomicAdd(ab+1, v.y*w);
  atomicAdd(ab+2, v.z*w);
  atomicAdd(ab+3, v.w*w);
}

// ---------------- epilogue: LN((agg/z)@Wo^T + indeg*bo + deg + x) ----------------
__global__ __launch_bounds__(256,1) void k_out_mma(
    const float* __restrict__ agg, const float* __restrict__ z,
    const float* __restrict__ W, const float* __restrict__ bias,
    const int* __restrict__ indeg, const int* __restrict__ deg,
    const float* __restrict__ xres, float* __restrict__ out){
  extern __shared__ uint32_t sm[];
  int tid = threadIdx.x, lane = tid & 31, wid = tid >> 5;
  int mw = wid & 3, nw = wid >> 2, tg = lane >> 2, tq = lane & 3;
  int row0 = blockIdx.x * MT;

  // stage A = agg / z
  #pragma unroll
  for (int it = 0; it < 32; it++){
    int idx = tid + it*256;
    int row = idx >> 6, j = idx & 63;
    float2 v = make_float2(0.f, 0.f);
    int gr = row0 + row;
    if (gr < NN){
      float zz = z[(size_t)gr*HH + (j >> 4)];
      float inv = (zz > 0.f) ? (1.f/zz) : 0.f;
      float2 a = *(const float2*)(agg + (size_t)gr*CC + j*2);
      v = make_float2(a.x*inv, a.y*inv);
    }
    uint32_t hi, lo;
    bsplit(v.x, v.y, hi, lo);
    sm[AHI + row*PITCH + j] = hi;
    sm[ALO + row*PITCH + j] = lo;
  }
  stage_mat(sm, BHI, BLO, W, 0, false);
  __syncthreads();

  float acc[2][8][4];
  #pragma unroll
  for (int a=0;a<2;a++)
    #pragma unroll
    for (int b=0;b<8;b++)
      #pragma unroll
      for (int c=0;c<4;c++) acc[a][b][c]=0.f;

  mma_core(sm, acc, mw, nw, tg, tq);

  float* reds = (float*)(sm + REDS);
  float* redq = (float*)(sm + REDQ);

  float2 bb[8];
  #pragma unroll
  for (int nt = 0; nt < 8; nt++) bb[nt] = *(const float2*)(bias + nw*64 + nt*8 + tq*2);

  // add bias*indeg + deg + residual; accumulate row sums
  #pragma unroll
  for (int mt = 0; mt < 2; mt++){
    #pragma unroll
    for (int h = 0; h < 2; h++){
      int lr = mw*32 + mt*16 + tg + h*8;
      int grow = row0 + lr;
      float dg = 0.f, idg = 0.f;
      if (grow < NN){ dg = (float)deg[grow]; idg = (float)indeg[grow]; }
      float s = 0.f;
      #pragma unroll
      for (int nt = 0; nt < 8; nt++){
        int col = nw*64 + nt*8 + tq*2;
        float2 xr = make_float2(0.f, 0.f);
        if (grow < NN) xr = *(const float2*)(xres + (size_t)grow*CC + col);
        float v0 = acc[mt][nt][h*2+0] + bb[nt].x*idg + dg + xr.x;
        float v1 = acc[mt][nt][h*2+1] + bb[nt].y*idg + dg + xr.y;
        acc[mt][nt][h*2+0] = v0;
        acc[mt][nt][h*2+1] = v1;
        s += v0 + v1;
      }
      s += __shfl_xor_sync(0xffffffffu, s, 1);
      s += __shfl_xor_sync(0xffffffffu, s, 2);
      if (tq == 0) reds[lr*2 + nw] = s;
    }
  }
  __syncthreads();

  float mu[2][2];
  #pragma unroll
  for (int mt = 0; mt < 2; mt++)
    #pragma unroll
    for (int h = 0; h < 2; h++){
      int lr = mw*32 + mt*16 + tg + h*8;
      mu[mt][h] = (reds[lr*2] + reds[lr*2+1]) * (1.f/128.f);
    }

  #pragma unroll
  for (int mt = 0; mt < 2; mt++){
    #pragma unroll
    for (int h = 0; h < 2; h++){
      int lr = mw*32 + mt*16 + tg + h*8;
      float q = 0.f;
      #pragma unroll
      for (int nt = 0; nt < 8; nt++){
        float d0 = acc[mt][nt][h*2+0] - mu[mt][h];
        float d1 = acc[mt][nt][h*2+1] - mu[mt][h];
        q += d0*d0 + d1*d1;
      }
      q += __shfl_xor_sync(0xffffffffu, q, 1);
      q += __shfl_xor_sync(0xffffffffu, q, 2);
      if (tq == 0) redq[lr*2 + nw] = q;
    }
  }
  __syncthreads();

  #pragma unroll
  for (int mt = 0; mt < 2; mt++){
    #pragma unroll
    for (int h = 0; h < 2; h++){
      int lr = mw*32 + mt*16 + tg + h*8;
      int grow = row0 + lr;
      if (grow >= NN) continue;
      float var = (redq[lr*2] + redq[lr*2+1]) * (1.f/128.f);
      float rs = rsqrtf(var + 1e-5f);
      float m = mu[mt][h];
      #pragma unroll
      for (int nt = 0; nt < 8; nt++){
        int col = nw*64 + nt*8 + tq*2;
        *(float2*)(out + (size_t)grow*CC + col) =
          make_float2((acc[mt][nt][h*2+0]-m)*rs, (acc[mt][nt][h*2+1]-m)*rs);
      }
    }
  }
}

// ---------------- launch ----------------
extern "C" void kernel_launch(void* const* d_in, const int* in_sizes, int n_in,
                              void* d_out, int out_size){
  const float* x_user=(const float*)d_in[0];
  const float* x_item=(const float*)d_in[1];
  const float* t_user=(const float*)d_in[2];
  const float* t_item=(const float*)d_in[3];
  const int*   eui  =(const int*)  d_in[4];
  const int*   eiu  =(const int*)  d_in[5];
  const float* Wq=(const float*)d_in[6];  const float* bq=(const float*)d_in[7];
  const float* Wk=(const float*)d_in[8];  const float* bk=(const float*)d_in[9];
  const float* Wv=(const float*)d_in[10]; const float* bv=(const float*)d_in[11];
  const float* Wo=(const float*)d_in[12]; const float* bo=(const float*)d_in[13];
  const float* hb=(const float*)d_in[14];
  const float* tb=(const float*)d_in[15];
  const float* traw=(const float*)d_in[16];
  const float* gm=(const float*)d_in[17];
  const float* dr=(const float*)d_in[18];
  float* out=(float*)d_out;

  float *Qu,*Ku,*Vu,*Qi,*Ki,*Vi,*aggu,*aggi,*zu,*zi;
  int *cku,*cvu,*cki,*cvi,*rku,*rki,*degu,*degi,*idgu,*idgi;
  cudaGetSymbolAddress((void**)&Qu, g_Qu);
  cudaGetSymbolAddress((void**)&Ku, g_Ku);
  cudaGetSymbolAddress((void**)&Vu, g_Vu);
  cudaGetSymbolAddress((void**)&Qi, g_Qi);
  cudaGetSymbolAddress((void**)&Ki, g_Ki);
  cudaGetSymbolAddress((void**)&Vi, g_Vi);
  cudaGetSymbolAddress((void**)&aggu, g_agg_u);
  cudaGetSymbolAddress((void**)&aggi, g_agg_i);
  cudaGetSymbolAddress((void**)&zu, g_z_u);
  cudaGetSymbolAddress((void**)&zi, g_z_i);
  cudaGetSymbolAddress((void**)&cku, g_ck_ui);
  cudaGetSymbolAddress((void**)&cvu, g_cv_ui);
  cudaGetSymbolAddress((void**)&cki, g_ck_iu);
  cudaGetSymbolAddress((void**)&cvi, g_cv_iu);
  cudaGetSymbolAddress((void**)&rku, g_rk_ui);
  cudaGetSymbolAddress((void**)&rki, g_rk_iu);
  cudaGetSymbolAddress((void**)&degu, g_deg_u);
  cudaGetSymbolAddress((void**)&degi, g_deg_i);
  cudaGetSymbolAddress((void**)&idgu, g_indeg_u);
  cudaGetSymbolAddress((void**)&idgi, g_indeg_i);

  cudaFuncSetAttribute(k_qkv3,   cudaFuncAttributeMaxDynamicSharedMemorySize, SMEMB);
  cudaFuncSetAttribute(k_out_mma,cudaFuncAttributeMaxDynamicSharedMemorySize, SMEMB);

  k_init<<<2048,256>>>();
  k_build<<<(2*EE+255)/256,256>>>(eui, eiu);

  // fused QKV projections (tensor path, bf16-split = fp32-accurate)
  k_qkv3<<<NBLK,256,SMEMB>>>(x_user, Wq,Wk,Wv, bq,bk,bv, Qu,Ku,Vu);
  k_qkv3<<<NBLK,256,SMEMB>>>(x_item, Wq,Wk,Wv, bq,bk,bv, Qi,Ki,Vi);

  // relation user->item (rel 0): Q from items (dst), K/V from users (src)
  k_edge<<<EE/8,256>>>(eui, eui+EE, Qi, Ku, Vu, t_user, t_item,
                       cku, cvu, rku, hb, tb, traw, gm, dr, zi, aggi);
  // relation item->user (rel 1)
  k_edge<<<EE/8,256>>>(eiu, eiu+EE, Qu, Ki, Vi, t_item, t_user,
                       cki, cvi, rki, hb+HH, tb+HH, traw+1, gm+HH, dr+HH, zu, aggu);

  // fused Wo + indeg*bo + deg + residual + layernorm
  k_out_mma<<<NBLK,256,SMEMB>>>(aggu, zu, Wo, bo, idgu, degu, x_user, out);
  k_out_mma<<<NBLK,256,SMEMB>>>(aggi, zi, Wo, bo, idgi, degi, x_item, out + (size_t)NN*CC);
}